// round 5
// baseline (speedup 1.0000x reference)
#include <cuda_runtime.h>
#include <cuda_bf16.h>

// loss = (1/B) * sum_rows sum_{a<j in rank order} |t_a - t_j| * (dv_j - dv_a),  dv_k = log2(k+3)
// (sigmoid eliminated via sigma(x)+sigma(-x)=1; dv monotone in rank.)
// Single fused kernel, one block per row:
//  P0: bitonic sort by pred desc (payload target)  -> st[] rank-ordered targets
//  P1: per 128-tile bitonic sort by target (payload rank) -> ts[], and (t, dv, t*dv)
//  P2: segmented inclusive scans of (t, dv, t*dv) per tile
//  P3: per a: diag tile brute force (packed f32x2) + per later tile: binary search + O(1) combine

constexpr int BB = 32;
constexpr int NN = 2048;
constexpr int TS = 128;
constexpr int NT = NN / TS;   // 16

typedef unsigned long long ull;

__global__ void zero_kernel(float* out) { if (threadIdx.x == 0) out[0] = 0.0f; }

// ---------- packed f32x2 helpers ----------
__device__ __forceinline__ ull pk2(float lo, float hi) {
    ull r; asm("mov.b64 %0, {%1, %2};" : "=l"(r) : "f"(lo), "f"(hi)); return r;
}
__device__ __forceinline__ float sum2(ull v) {
    float lo, hi; asm("mov.b64 {%0, %1}, %2;" : "=f"(lo), "=f"(hi) : "l"(v));
    return lo + hi;
}
__device__ __forceinline__ ull add2(ull a, ull b) {
    ull r; asm("add.rn.f32x2 %0, %1, %2;" : "=l"(r) : "l"(a), "l"(b)); return r;
}
__device__ __forceinline__ ull fma2(ull a, ull b, ull c) {
    ull r; asm("fma.rn.f32x2 %0, %1, %2, %3;" : "=l"(r) : "l"(a), "l"(b), "l"(c)); return r;
}
__device__ __forceinline__ ull abs2(ull a) { return a & 0x7fffffff7fffffffULL; }

__device__ __forceinline__ ull cex(ull v, ull o, int p, int j, int k) {
    bool up  = ((p & k) == 0);
    bool low = ((p & j) == 0);
    ull mn = (v < o) ? v : o;
    ull mx = (v < o) ? o : v;
    return (low == up) ? mn : mx;
}

union USort {
    ull dbuf[2][NN];                                            // 32KB: P0/P1 staging
    struct { float Pt[NN]; float Pw[NN]; float Ptw[NN]; float ts[NN]; } q;  // 32KB: P2/P3
};

__global__ void __launch_bounds__(1024) fused_kernel(const float* __restrict__ preds,
                                                     const float* __restrict__ targets,
                                                     float* __restrict__ out) {
    __shared__ USort S;
    __shared__ alignas(16) float st[NN];    // targets in rank order
    __shared__ alignas(16) float dvr[NN];   // dv by rank

    const int row = blockIdx.x;
    const int t   = threadIdx.x;

    dvr[t]        = __log2f((float)(t + 3));
    dvr[t + 1024] = __log2f((float)(t + 1024 + 3));

    // ---- P0: bitonic sort by pred descending, payload = target bits ----
    const float* p  = preds + row * NN;
    const float* tv = targets + row * NN;
    unsigned u0 = __float_as_uint(p[t]);
    u0 = (u0 & 0x80000000u) ? ~u0 : (u0 | 0x80000000u);
    ull v0 = ((ull)(~u0) << 32) | (ull)__float_as_uint(tv[t]);
    unsigned u1 = __float_as_uint(p[t + 1024]);
    u1 = (u1 & 0x80000000u) ? ~u1 : (u1 | 0x80000000u);
    ull v1 = ((ull)(~u1) << 32) | (ull)__float_as_uint(tv[t + 1024]);

    int cur = 0;
#pragma unroll
    for (int k = 2; k <= NN; k <<= 1) {
#pragma unroll
        for (int j = k >> 1; j > 0; j >>= 1) {
            if (j == 1024) {
                ull mn = (v0 < v1) ? v0 : v1;
                ull mx = (v0 < v1) ? v1 : v0;
                v0 = mn; v1 = mx;
            } else if (j >= 32) {
                S.dbuf[cur][t] = v0; S.dbuf[cur][t + 1024] = v1;
                __syncthreads();
                ull o0 = S.dbuf[cur][t ^ j];
                ull o1 = S.dbuf[cur][(t + 1024) ^ j];
                v0 = cex(v0, o0, t, j, k);
                v1 = cex(v1, o1, t + 1024, j, k);
                cur ^= 1;
            } else {
                ull o0 = __shfl_xor_sync(0xffffffffu, v0, j);
                v0 = cex(v0, o0, t, j, k);
                ull o1 = __shfl_xor_sync(0xffffffffu, v1, j);
                v1 = cex(v1, o1, t + 1024, j, k);
            }
        }
    }

    // rank-ordered targets (position t / t+1024 = rank)
    const float st0 = __uint_as_float((unsigned)v0);
    const float st1 = __uint_as_float((unsigned)v1);
    st[t] = st0; st[t + 1024] = st1;

    // ---- P1: per-128-tile bitonic sort by target asc, payload = rank ----
    unsigned m0 = __float_as_uint(st0);
    m0 = (m0 & 0x80000000u) ? ~m0 : (m0 | 0x80000000u);
    ull w0 = ((ull)m0 << 32) | (unsigned)t;
    unsigned m1 = __float_as_uint(st1);
    m1 = (m1 & 0x80000000u) ? ~m1 : (m1 | 0x80000000u);
    ull w1 = ((ull)m1 << 32) | (unsigned)(t + 1024);

    const int l = t & (TS - 1);   // local index within tile (same for both elements)
#pragma unroll
    for (int k = 2; k <= TS; k <<= 1) {
#pragma unroll
        for (int j = k >> 1; j > 0; j >>= 1) {
            if (j >= 32) {
                S.dbuf[cur][t] = w0; S.dbuf[cur][t + 1024] = w1;
                __syncthreads();
                ull o0 = S.dbuf[cur][t ^ j];
                ull o1 = S.dbuf[cur][(t + 1024) ^ j];
                w0 = cex(w0, o0, l, j, k);
                w1 = cex(w1, o1, l, j, k);
                cur ^= 1;
            } else {
                ull o0 = __shfl_xor_sync(0xffffffffu, w0, j);
                w0 = cex(w0, o0, l, j, k);
                ull o1 = __shfl_xor_sync(0xffffffffu, w1, j);
                w1 = cex(w1, o1, l, j, k);
            }
        }
    }
    __syncthreads();   // all dbuf reads done before overwriting with q.*

    // unpack: key hi -> t value, payload -> rank -> dv
    {
        unsigned h0 = (unsigned)(w0 >> 32);
        unsigned o0 = (h0 & 0x80000000u) ? (h0 & 0x7fffffffu) : ~h0;
        float tt0 = __uint_as_float(o0);
        float dd0 = dvr[(unsigned)w0 & 0x7ffu];
        S.q.ts[t] = tt0; S.q.Pt[t] = tt0; S.q.Pw[t] = dd0; S.q.Ptw[t] = tt0 * dd0;

        unsigned h1 = (unsigned)(w1 >> 32);
        unsigned o1 = (h1 & 0x80000000u) ? (h1 & 0x7fffffffu) : ~h1;
        float tt1 = __uint_as_float(o1);
        float dd1 = dvr[(unsigned)w1 & 0x7ffu];
        S.q.ts[t + 1024] = tt1; S.q.Pt[t + 1024] = tt1;
        S.q.Pw[t + 1024] = dd1; S.q.Ptw[t + 1024] = tt1 * dd1;
    }
    __syncthreads();

    // ---- P2: segmented inclusive scans (Hillis-Steele) within each tile ----
#pragma unroll
    for (int off = 1; off < TS; off <<= 1) {
        bool g = (l >= off);
        float a0 = g ? S.q.Pt [t - off] : 0.f;
        float b0 = g ? S.q.Pw [t - off] : 0.f;
        float c0 = g ? S.q.Ptw[t - off] : 0.f;
        float a1 = g ? S.q.Pt [t + 1024 - off] : 0.f;
        float b1 = g ? S.q.Pw [t + 1024 - off] : 0.f;
        float c1 = g ? S.q.Ptw[t + 1024 - off] : 0.f;
        __syncthreads();
        if (g) {
            S.q.Pt [t] += a0; S.q.Pw [t] += b0; S.q.Ptw[t] += c0;
            S.q.Pt [t + 1024] += a1; S.q.Pw [t + 1024] += b1; S.q.Ptw[t + 1024] += c1;
        }
        __syncthreads();
    }

    // ---- P3: queries + diagonal ----
    float res = 0.f;
#pragma unroll
    for (int ii = 0; ii < 2; ii++) {
        const int a = t + ii * 1024;
        const float ta = st[a];
        const float da = dvr[a];
        const int ia = a >> 7;
        const int e_end = (ia + 1) << 7;

        // diagonal: j in (a, tile_end), rank order, dv_j > da
        if (!(a & 1) && a + 1 < e_end) {
            float u = fabsf(st[a + 1] - ta);
            res += u * (dvr[a + 1] - da);
        }
        const ull nta = pk2(-ta, -ta);
        const ull* ps = (const ull*)st;
        const ull* pd = (const ull*)dvr;
        ull h0 = 0, h1 = 0;
        const int s0 = (a + 2) & ~1;
        for (int jj = (s0 >> 1); jj < (e_end >> 1); jj++) {
            ull uu = abs2(add2(ps[jj], nta));
            h1 = fma2(uu, pd[jj], h1);
            h0 = add2(h0, uu);
        }
        res += sum2(h1) - da * sum2(h0);

        // later tiles: binary search + prefix combine
        for (int jt = ia + 1; jt < NT; jt++) {
            const int b = jt << 7;
            int c = 0;
#pragma unroll
            for (int s = TS / 2; s > 0; s >>= 1)
                if (S.q.ts[b + c + s - 1] <= ta) c += s;
            float St = c ? S.q.Pt [b + c - 1] : 0.f;
            float Sw = c ? S.q.Pw [b + c - 1] : 0.f;
            float Sx = c ? S.q.Ptw[b + c - 1] : 0.f;
            float Tt = S.q.Pt [b + TS - 1];
            float Tw = S.q.Pw [b + TS - 1];
            float Tx = S.q.Ptw[b + TS - 1];
            float A  = ta * (float)(2 * c - TS) - 2.f * St + Tt;
            float Bq = ta * (2.f * Sw - Tw) - 2.f * Sx + Tx;
            res += Bq - da * A;
        }
    }

    // ---- block reduction ----
#pragma unroll
    for (int off = 16; off > 0; off >>= 1)
        res += __shfl_down_sync(0xffffffffu, res, off);
    __syncthreads();               // st reads done; reuse st[0..31] as wsum
    float* wsum = st;
    if ((t & 31) == 0) wsum[t >> 5] = res;
    __syncthreads();
    if (t == 0) {
        float bs = 0.f;
#pragma unroll
        for (int w = 0; w < 32; w++) bs += wsum[w];
        atomicAdd(out, bs * (1.0f / (float)BB));
    }
}

extern "C" void kernel_launch(void* const* d_in, const int* in_sizes, int n_in,
                              void* d_out, int out_size) {
    const float* preds   = (const float*)d_in[0];
    const float* targets = (const float*)d_in[1];
    float* out = (float*)d_out;

    zero_kernel<<<1, 32>>>(out);
    fused_kernel<<<BB, 1024>>>(preds, targets, out);
}

// round 6
// speedup vs baseline: 1.4058x; 1.4058x over previous
#include <cuda_runtime.h>
#include <cuda_bf16.h>

// loss = (1/B) * sum_rows sum_{rank i<j} |t_i - t_j| * (dv_j - dv_i),  dv_k = log2(k+3)
// Factor dv out:  loss_row = sum_k dv_k * (2*L_k - F_k),
//   L_k = sum_{rank i<k} |t_i - t_k|,  F_k = sum_{all i} |t_i - t_k|
// Tile ranks into 16 x 128. Per tile (target-sorted + prefix sums), for any query t:
//   A(t) = sum_{i in tile} |t_i - t| = t*(2c-128) - 2*St(c) + Stot   (c = #{t_i <= t})
// 2L_k - F_k = sum_{tiles before own} A - sum_{own & later} A + 2*L_own(brute).
// K1: per-row bitonic sort by pred desc (payload target) -> g_st (rank-ordered targets)
// K1b: per 128-tile sort targets asc + inclusive scan -> g_ts, g_pt
// K2: per element: 16 interleaved binary searches + O(1) combines + in-tile brute, x dv.

constexpr int BB = 32;
constexpr int NN = 2048;
constexpr int TS = 128;
constexpr int NT = NN / TS;   // 16

typedef unsigned long long ull;

__device__ float g_st[BB * NN];
__device__ float g_ts[BB * NN];
__device__ float g_pt[BB * NN];

__device__ __forceinline__ unsigned mono32(unsigned u) {
    return (u & 0x80000000u) ? ~u : (u | 0x80000000u);
}
__device__ __forceinline__ float unmono32(unsigned m) {
    unsigned o = (m & 0x80000000u) ? (m & 0x7fffffffu) : ~m;
    return __uint_as_float(o);
}

__device__ __forceinline__ ull cex64(ull v, ull o, int p, int j, int k) {
    bool up  = ((p & k) == 0);
    bool low = ((p & j) == 0);
    ull mn = (v < o) ? v : o;
    ull mx = (v < o) ? o : v;
    return (low == up) ? mn : mx;
}
__device__ __forceinline__ unsigned cex32(unsigned v, unsigned o, int p, int j, int k) {
    bool up  = ((p & k) == 0);
    bool low = ((p & j) == 0);
    unsigned mn = (v < o) ? v : o;
    unsigned mx = (v < o) ? o : v;
    return (low == up) ? mn : mx;
}

// ---------- K1: per-row bitonic sort by pred descending (payload = target) ----------
__global__ void __launch_bounds__(1024) sort_kernel(const float* __restrict__ preds,
                                                    const float* __restrict__ targets,
                                                    float* __restrict__ out) {
    __shared__ ull dbuf[2][NN];   // 32KB double buffer
    const int row = blockIdx.x;
    const int t = threadIdx.x;
    if (row == 0 && t == 0) out[0] = 0.0f;   // stream-ordered before K2's atomics

    const float2 pv = ((const float2*)(preds + row * NN))[t];
    const float2 tv = ((const float2*)(targets + row * NN))[t];

    // descending-pred key: ~mono32(pred bits); payload = target bits
    ull v0 = ((ull)(~mono32(__float_as_uint(pv.x))) << 32) | (ull)__float_as_uint(tv.x);
    ull v1 = ((ull)(~mono32(__float_as_uint(pv.y))) << 32) | (ull)__float_as_uint(tv.y);

    const int i0 = 2 * t, i1 = 2 * t + 1;   // contiguous element mapping
    int cur = 0;
#pragma unroll
    for (int k = 2; k <= NN; k <<= 1) {
#pragma unroll
        for (int j = k >> 1; j > 0; j >>= 1) {
            if (j == 1) {
                // both elements local to this thread
                bool up = ((i0 & k) == 0);
                ull mn = (v0 < v1) ? v0 : v1;
                ull mx = (v0 < v1) ? v1 : v0;
                v0 = up ? mn : mx;
                v1 = up ? mx : mn;
            } else if (j <= 32) {
                // partner thread = t ^ (j>>1), element pairing preserved
                int dt = j >> 1;
                ull o0 = __shfl_xor_sync(0xffffffffu, v0, dt);
                ull o1 = __shfl_xor_sync(0xffffffffu, v1, dt);
                v0 = cex64(v0, o0, i0, j, k);
                v1 = cex64(v1, o1, i1, j, k);
            } else {
                dbuf[cur][i0] = v0; dbuf[cur][i1] = v1;
                __syncthreads();
                ull o0 = dbuf[cur][i0 ^ j];
                ull o1 = dbuf[cur][i1 ^ j];
                v0 = cex64(v0, o0, i0, j, k);
                v1 = cex64(v1, o1, i1, j, k);
                cur ^= 1;
            }
        }
    }
    ((float2*)(g_st + row * NN))[t] =
        make_float2(__uint_as_float((unsigned)v0), __uint_as_float((unsigned)v1));
}

// ---------- K1b: per-tile target sort (keys only) + inclusive scan ----------
__global__ void __launch_bounds__(TS) tile_kernel() {
    __shared__ unsigned sb[TS];
    __shared__ float woff[4];
    const int row  = blockIdx.y;
    const int tile = blockIdx.x;
    const int tid  = threadIdx.x;

    float tval = g_st[row * NN + tile * TS + tid];
    unsigned m = mono32(__float_as_uint(tval));   // ascending

#pragma unroll
    for (int k = 2; k <= TS; k <<= 1) {
#pragma unroll
        for (int j = k >> 1; j > 0; j >>= 1) {
            if (j >= 32) {
                sb[tid] = m;
                __syncthreads();
                unsigned o = sb[tid ^ j];
                __syncthreads();
                m = cex32(m, o, tid, j, k);
            } else {
                unsigned o = __shfl_xor_sync(0xffffffffu, m, j);
                m = cex32(m, o, tid, j, k);
            }
        }
    }
    float tsv = unmono32(m);

    // inclusive scan across 128 threads
    const int lane = tid & 31, wid = tid >> 5;
    float x = tsv;
#pragma unroll
    for (int off = 1; off < 32; off <<= 1) {
        float y = __shfl_up_sync(0xffffffffu, x, off);
        if (lane >= off) x += y;
    }
    __shared__ float wt[4];
    if (lane == 31) wt[wid] = x;
    __syncthreads();
    if (tid == 0) {
        float s = 0.f;
#pragma unroll
        for (int w = 0; w < 4; w++) { woff[w] = s; s += wt[w]; }
    }
    __syncthreads();
    float ptv = x + woff[wid];

    const int gbase = (row * NT + tile) * TS;
    g_ts[gbase + tid] = tsv;
    g_pt[gbase + tid] = ptv;
}

// ---------- K2: per-element queries ----------
__global__ void __launch_bounds__(256) query_kernel(float* __restrict__ out) {
    __shared__ float ts_s[NN];
    __shared__ float pt_s[NN];
    __shared__ float st_s[256];
    __shared__ float wsum[8];

    const int row = blockIdx.y;
    const int ch  = blockIdx.x;      // 0..7, chunk of 256 ranks
    const int tid = threadIdx.x;

    for (int i = tid; i < NN; i += 256) {
        ts_s[i] = g_ts[row * NN + i];
        pt_s[i] = g_pt[row * NN + i];
    }
    st_s[tid] = g_st[row * NN + ch * 256 + tid];
    __syncthreads();

    const int a = ch * 256 + tid;
    const int T = a >> 7;                   // own tile
    const float ta = st_s[tid];
    const float da = __log2f((float)(a + 3));

    // 16 interleaved binary searches: c[tau] = #{t_i <= ta} in tile tau
    int c[NT];
#pragma unroll
    for (int u = 0; u < NT; u++) c[u] = 0;
#pragma unroll
    for (int s = TS / 2; s > 0; s >>= 1) {
#pragma unroll
        for (int u = 0; u < NT; u++) {
            if (ts_s[u * TS + c[u] + s - 1] <= ta) c[u] += s;
        }
    }

    float acc = 0.f;
#pragma unroll
    for (int u = 0; u < NT; u++) {
        int cc = c[u];
        float St   = cc ? pt_s[u * TS + cc - 1] : 0.f;
        float Stot = pt_s[u * TS + TS - 1];
        float A = ta * (float)(2 * cc - TS) - 2.f * St + Stot;
        acc += (u < T) ? A : -A;
    }

    // within-own-tile earlier-rank brute: L_own
    const int base = tid & TS;        // 0 or 128
    const int l    = tid & (TS - 1);  // local rank
    float L = 0.f;
    for (int i = 0; i < l; i++)
        L += fabsf(st_s[base + i] - ta);

    float res = da * (acc + 2.f * L);

#pragma unroll
    for (int off = 16; off > 0; off >>= 1)
        res += __shfl_down_sync(0xffffffffu, res, off);
    if ((tid & 31) == 0) wsum[tid >> 5] = res;
    __syncthreads();
    if (tid == 0) {
        float bs = 0.f;
#pragma unroll
        for (int w = 0; w < 8; w++) bs += wsum[w];
        atomicAdd(out, bs * (1.0f / (float)BB));
    }
}

extern "C" void kernel_launch(void* const* d_in, const int* in_sizes, int n_in,
                              void* d_out, int out_size) {
    const float* preds   = (const float*)d_in[0];
    const float* targets = (const float*)d_in[1];
    float* out = (float*)d_out;

    sort_kernel<<<BB, 1024>>>(preds, targets, out);

    dim3 g1(NT, BB);
    tile_kernel<<<g1, TS>>>();

    dim3 g2(NN / 256, BB);
    query_kernel<<<g2, 256>>>(out);
}